// round 13
// baseline (speedup 1.0000x reference)
#include <cuda_runtime.h>
#include <cuda_fp16.h>
#include <mma.h>
#include <cstdint>
#include <cstddef>

using namespace nvcuda;

#define NDIM  512
#define BATCH 65536
#define LDAB  72                     // halves per padded row (64 data + 8 pad)
#define CHUNK_H (128 * LDAB)         // halves per chunk tile (128 rows)
#define CHUNK_B (CHUNK_H * 2)        // 18432 bytes

// Scratch (__device__ globals: allocation-free rule). Chunk-contiguous padded
// layouts: [tile][chunk][row][72] so cp.async.bulk fetches one chunk per copy.
__device__ float  g_Wpart[16 * NDIM * NDIM];
__device__ __half g_Wc [4 * 8 * CHUNK_H];               // W^T  chunks [ntile][c][n][72]
__device__ __half g_W2c[4 * 8 * CHUNK_H];               // W2^T chunks
__device__ __half g_hc[(size_t)512 * 8 * CHUNK_H];      // h fp16 chunks

__device__ __forceinline__ uint32_t pack_h2(__half a, __half b) {
    return (uint32_t)__half_as_ushort(a) | ((uint32_t)__half_as_ushort(b) << 16);
}
__device__ __forceinline__ uint32_t smem_u32(const void* p) {
    uint32_t a;
    asm("{ .reg .u64 t; cvta.to.shared.u64 t, %1; cvt.u32.u64 %0, t; }" : "=r"(a) : "l"(p));
    return a;
}
#define MBAR_INIT(a, c) asm volatile("mbarrier.init.shared.b64 [%0], %1;" :: "r"(a), "r"(c) : "memory")
__device__ __forceinline__ void mbar_wait(uint32_t a, uint32_t ph) {
    uint32_t d;
    do {
        asm volatile("{ .reg .pred p; mbarrier.try_wait.parity.acquire.cta.shared::cta.b64 p, [%1], %2, 0x989680;"
                     " selp.b32 %0,1,0,p; }" : "=r"(d) : "r"(a), "r"(ph) : "memory");
    } while (!d);
}
__device__ __forceinline__ void mbar_expect_tx(uint32_t a, uint32_t bytes) {
    asm volatile("mbarrier.arrive.expect_tx.shared.b64 _, [%0], %1;" :: "r"(a), "r"(bytes) : "memory");
}
__device__ __forceinline__ void bulk_g2s(uint32_t dst, const void* src, uint32_t bytes, uint32_t mbar) {
    asm volatile("cp.async.bulk.shared::cluster.global.mbarrier::complete_tx::bytes [%0], [%1], %2, [%3];"
                 :: "r"(dst), "l"(src), "r"(bytes), "r"(mbar) : "memory");
}

// ---------------- Kernel 1: Krylov partial W (split by i and j-quarter) ----------------
// W[a,b] = sum_i sum_j ge_i[512+a-j] * hs_i[b+j]
__global__ __launch_bounds__(256)
void krylov_part(const float* __restrict__ G, const float* __restrict__ H,
                 float* __restrict__ Wp) {
    __shared__ float ge[1024], hs[1024];
    const int tid = threadIdx.x;
    const int i  = blockIdx.z & 3;
    const int j0 = (blockIdx.z >> 2) * 128;
    for (int k = tid; k < 1024; k += 256) {
        ge[k] = G[(k & 511) * 4 + i];
        hs[k] = (k < 512) ? H[k * 4 + i] : -H[(k - 512) * 4 + i];
    }
    __syncthreads();
    const int a0 = blockIdx.y * 64 + (tid >> 4) * 4;
    const int b0 = blockIdx.x * 64 + (tid & 15) * 4;
    float acc[4][4] = {};
    float ga[4], hb[4];
#pragma unroll
    for (int d = 0; d < 4; ++d) ga[d] = ge[512 + a0 + d - j0];
#pragma unroll
    for (int e = 0; e < 4; ++e) hb[e] = hs[b0 + e + j0];
#pragma unroll 4
    for (int j = j0; j < j0 + 128; ++j) {
#pragma unroll
        for (int d = 0; d < 4; ++d)
#pragma unroll
            for (int e = 0; e < 4; ++e)
                acc[d][e] = fmaf(ga[d], hb[e], acc[d][e]);
        ga[3] = ga[2]; ga[2] = ga[1]; ga[1] = ga[0];
        ga[0] = ge[512 + a0 - (j + 1)];
        hb[0] = hb[1]; hb[1] = hb[2]; hb[2] = hb[3];
        hb[3] = hs[b0 + 3 + (j + 1)];
    }
    float* Ws = Wp + (size_t)blockIdx.z * NDIM * NDIM;
#pragma unroll
    for (int d = 0; d < 4; ++d)
#pragma unroll
        for (int e = 0; e < 4; ++e)
            Ws[(a0 + d) * NDIM + (b0 + e)] = acc[d][e];
}

// ---------------- Kernel 2: fused pack (W-sum+transpose | W2 transpose) ----------------
__global__ __launch_bounds__(256)
void pack_both(const float* __restrict__ Wp, __half* __restrict__ Wc,
               const float* __restrict__ W2, __half* __restrict__ W2c) {
    __shared__ float t[32][33];
    const int which = blockIdx.x >> 8;
    const int b = blockIdx.x & 255;
    const int bx = (b & 15) * 32, by = (b >> 4) * 32;
    const int tx = threadIdx.x & 31, ty = threadIdx.x >> 5;
    if (which == 0) {
        for (int r = ty; r < 32; r += 8) {
            size_t o = (size_t)(bx + r) * NDIM + by + tx;
            float s = 0.f;
#pragma unroll
            for (int z = 0; z < 16; ++z) s += Wp[o + (size_t)z * NDIM * NDIM];
            t[r][tx] = s;
        }
        __syncthreads();
        for (int r = ty; r < 32; r += 8) {
            int n = by + r, k = bx + tx;
            size_t off = ((size_t)((n >> 7) * 8 + (k >> 6)) * 128 + (n & 127)) * LDAB + (k & 63);
            Wc[off] = __float2half_rn(t[tx][r]);
        }
    } else {
        for (int r = ty; r < 32; r += 8)
            t[r][tx] = W2[(size_t)(bx + r) * NDIM + by + tx];
        __syncthreads();
        for (int r = ty; r < 32; r += 8) {
            int n = by + r, k = bx + tx;
            size_t off = ((size_t)((n >> 7) * 8 + (k >> 6)) * 128 + (n & 127)) * LDAB + (k & 63);
            W2c[off] = __float2half_rn(t[tx][r]);
        }
    }
}

// ---------------- GEMM common config ----------------
#define STG_SZ  36864u               // A chunk (18432) + B chunk (18432)
#define SBIAS   110592u
#define SMBAR   111104u
#define SMEM_SZ 111136u
#define NCHUNK  8

// ---------------- Kernel 3: GEMM1 — A = x fp32 converted inline, B via bulk ----------------
// C = relu(acc + b1) -> h chunks.
__global__ __launch_bounds__(128, 2)
void gemm1(const float* __restrict__ x, const __half* __restrict__ Bg,
           const float* __restrict__ bias, __half* __restrict__ hc) {
    extern __shared__ char smem[];
    const uint32_t sb = smem_u32(smem);
    __half* smh = (__half*)smem;
    const int tid = threadIdx.x;
    const int w  = tid >> 5;
    const int wm = w >> 1;
    const int wn = w & 1;
    const int bx = blockIdx.x, mt = blockIdx.y;
    const int n0 = bx * 128, m0 = mt * 128;

    float* bias_s = (float*)(smem + SBIAS);
    if (tid < 128) bias_s[tid] = bias[n0 + tid];
    if (tid == 0) {
#pragma unroll
        for (int s = 0; s < 3; ++s) MBAR_INIT(sb + SMBAR + s * 8, 1);
    }
    __syncthreads();

    auto issueB = [&](int c) {       // tid 0 only
        uint32_t mb  = sb + SMBAR + (c % 3) * 8;
        uint32_t buf = sb + (uint32_t)(c % 3) * STG_SZ;
        mbar_expect_tx(mb, CHUNK_B);
        bulk_g2s(buf + CHUNK_B, Bg + ((size_t)bx * 8 + c) * CHUNK_H, CHUNK_B, mb);
    };
    if (tid == 0) { issueB(0); issueB(1); }

    // ---- inline A path: 128 rows x 64 f32 per chunk; thread covers 8 rows x 8 f32 ----
    const int rn = tid >> 3;         // 0..15
    const int sg = tid & 7;          // 8 f32 per segment
    const float* xbase = x + (size_t)m0 * NDIM + sg * 8;
    uint32_t pk[32];                 // one chunk of packed fp16 (prefetch regs)

    auto ldA = [&](int c) {
#pragma unroll
        for (int q = 0; q < 8; ++q) {
            const float* p = xbase + (size_t)(rn + q * 16) * NDIM + c * 64;
            float4 u = *(const float4*)p;
            float4 v = *(const float4*)(p + 4);
            pk[q * 4 + 0] = pack_h2(__float2half_rn(u.x), __float2half_rn(u.y));
            pk[q * 4 + 1] = pack_h2(__float2half_rn(u.z), __float2half_rn(u.w));
            pk[q * 4 + 2] = pack_h2(__float2half_rn(v.x), __float2half_rn(v.y));
            pk[q * 4 + 3] = pack_h2(__float2half_rn(v.z), __float2half_rn(v.w));
        }
    };
    auto stA = [&](int c) {
        char* buf = smem + (c % 3) * STG_SZ;
#pragma unroll
        for (int q = 0; q < 8; ++q)
            *(uint4*)(buf + (rn + q * 16) * (LDAB * 2) + sg * 16) =
                make_uint4(pk[q * 4], pk[q * 4 + 1], pk[q * 4 + 2], pk[q * 4 + 3]);
    };
    ldA(0); stA(0); ldA(1);          // pre-loop: buf0 A filled, chunk1 in regs

    wmma::fragment<wmma::accumulator, 16, 16, 16, float> acc[4][4];
#pragma unroll
    for (int i = 0; i < 4; ++i)
#pragma unroll
        for (int j = 0; j < 4; ++j)
            wmma::fill_fragment(acc[i][j], 0.f);

    for (int c = 0; c < NCHUNK; ++c) {
        mbar_wait(sb + SMBAR + (c % 3) * 8, (c / 3) & 1);
        __syncthreads();             // A(c) stores + B(c) TMA visible; (c+2)%3 consumed
        if (tid == 0 && c + 2 < NCHUNK) issueB(c + 2);
        if (c + 1 < NCHUNK) {        // stage A(c+1); prefetch A(c+2)
            stA(c + 1);              // writes buf (c+1)%3 == (c-2)%3: consumed pre-barrier
            if (c + 2 < NCHUNK) ldA(c + 2);
        }

        const __half* As = smh + ((c % 3) * STG_SZ) / 2;
        const __half* Bs = As + CHUNK_H;
#pragma unroll
        for (int kk = 0; kk < 4; ++kk) {
            wmma::fragment<wmma::matrix_a, 16, 16, 16, __half, wmma::row_major> af[4];
            wmma::fragment<wmma::matrix_b, 16, 16, 16, __half, wmma::col_major> bf[4];
#pragma unroll
            for (int i = 0; i < 4; ++i)
                wmma::load_matrix_sync(af[i], As + (wm * 64 + i * 16) * LDAB + kk * 16, LDAB);
#pragma unroll
            for (int j = 0; j < 4; ++j)
                wmma::load_matrix_sync(bf[j], Bs + (wn * 64 + j * 16) * LDAB + kk * 16, LDAB);
#pragma unroll
            for (int i = 0; i < 4; ++i)
#pragma unroll
                for (int j = 0; j < 4; ++j)
                    wmma::mma_sync(acc[i][j], af[i], bf[j], acc[i][j]);
        }
    }
    __syncthreads();

    // ---- epilogue: accs -> SMEM fp32, relu+bias -> h chunks ----
    float* Cs = (float*)smem;
#pragma unroll
    for (int i = 0; i < 4; ++i)
#pragma unroll
        for (int j = 0; j < 4; ++j)
            wmma::store_matrix_sync(Cs + (wm * 64 + i * 16) * 132 + wn * 64 + j * 16,
                                    acc[i][j], 132, wmma::mem_row_major);
    __syncthreads();

    const int r = tid;
    const float* src = Cs + r * 132;
#pragma unroll
    for (int j = 0; j < 128; j += 8) {
        uint4 o;
        float v0 = fmaxf(src[j+0] + bias_s[j+0], 0.f), v1 = fmaxf(src[j+1] + bias_s[j+1], 0.f);
        float v2 = fmaxf(src[j+2] + bias_s[j+2], 0.f), v3 = fmaxf(src[j+3] + bias_s[j+3], 0.f);
        float v4 = fmaxf(src[j+4] + bias_s[j+4], 0.f), v5 = fmaxf(src[j+5] + bias_s[j+5], 0.f);
        float v6 = fmaxf(src[j+6] + bias_s[j+6], 0.f), v7 = fmaxf(src[j+7] + bias_s[j+7], 0.f);
        o.x = pack_h2(__float2half_rn(v0), __float2half_rn(v1));
        o.y = pack_h2(__float2half_rn(v2), __float2half_rn(v3));
        o.z = pack_h2(__float2half_rn(v4), __float2half_rn(v5));
        o.w = pack_h2(__float2half_rn(v6), __float2half_rn(v7));
        size_t off = ((size_t)(mt * 8 + bx * 2 + (j >> 6)) * 128 + r) * LDAB + (j & 63);
        *(uint4*)(hc + off) = o;
    }
}

// ---------------- Kernel 4: GEMM2 — both operands via bulk (r9 mainloop) ----------------
__global__ __launch_bounds__(128, 2)
void gemm2(const __half* __restrict__ Ag, const __half* __restrict__ Bg,
           const float* __restrict__ bias, float* __restrict__ out) {
    extern __shared__ char smem[];
    const uint32_t sb = smem_u32(smem);
    __half* smh = (__half*)smem;
    const int tid = threadIdx.x;
    const int w  = tid >> 5;
    const int wm = w >> 1;
    const int wn = w & 1;
    const int bx = blockIdx.x, mt = blockIdx.y;
    const int n0 = bx * 128, m0 = mt * 128;

    float* bias_s = (float*)(smem + SBIAS);
    if (tid < 128) bias_s[tid] = bias[n0 + tid];
    if (tid == 0) {
#pragma unroll
        for (int s = 0; s < 3; ++s) MBAR_INIT(sb + SMBAR + s * 8, 1);
    }
    __syncthreads();

    auto issue = [&](int c) {
        uint32_t mb  = sb + SMBAR + (c % 3) * 8;
        uint32_t buf = sb + (uint32_t)(c % 3) * STG_SZ;
        mbar_expect_tx(mb, 2 * CHUNK_B);
        bulk_g2s(buf,           Ag + ((size_t)mt * 8 + c) * CHUNK_H, CHUNK_B, mb);
        bulk_g2s(buf + CHUNK_B, Bg + ((size_t)bx * 8 + c) * CHUNK_H, CHUNK_B, mb);
    };
    if (tid == 0) { issue(0); issue(1); }

    wmma::fragment<wmma::accumulator, 16, 16, 16, float> acc[4][4];
#pragma unroll
    for (int i = 0; i < 4; ++i)
#pragma unroll
        for (int j = 0; j < 4; ++j)
            wmma::fill_fragment(acc[i][j], 0.f);

    for (int c = 0; c < NCHUNK; ++c) {
        mbar_wait(sb + SMBAR + (c % 3) * 8, (c / 3) & 1);
        __syncthreads();
        if (tid == 0 && c + 2 < NCHUNK) issue(c + 2);

        const __half* As = smh + ((c % 3) * STG_SZ) / 2;
        const __half* Bs = As + CHUNK_H;
#pragma unroll
        for (int kk = 0; kk < 4; ++kk) {
            wmma::fragment<wmma::matrix_a, 16, 16, 16, __half, wmma::row_major> af[4];
            wmma::fragment<wmma::matrix_b, 16, 16, 16, __half, wmma::col_major> bf[4];
#pragma unroll
            for (int i = 0; i < 4; ++i)
                wmma::load_matrix_sync(af[i], As + (wm * 64 + i * 16) * LDAB + kk * 16, LDAB);
#pragma unroll
            for (int j = 0; j < 4; ++j)
                wmma::load_matrix_sync(bf[j], Bs + (wn * 64 + j * 16) * LDAB + kk * 16, LDAB);
#pragma unroll
            for (int i = 0; i < 4; ++i)
#pragma unroll
                for (int j = 0; j < 4; ++j)
                    wmma::mma_sync(acc[i][j], af[i], bf[j], acc[i][j]);
        }
    }
    __syncthreads();

    float* Cs = (float*)smem;
#pragma unroll
    for (int i = 0; i < 4; ++i)
#pragma unroll
        for (int j = 0; j < 4; ++j)
            wmma::store_matrix_sync(Cs + (wm * 64 + i * 16) * 132 + wn * 64 + j * 16,
                                    acc[i][j], 132, wmma::mem_row_major);
    __syncthreads();

    const int r = tid;
    const float* src = Cs + r * 132;
    float* dst = out + (size_t)(m0 + r) * NDIM + n0;
#pragma unroll
    for (int j = 0; j < 128; j += 4) {
        float4 o;
        o.x = src[j+0] + bias_s[j+0];
        o.y = src[j+1] + bias_s[j+1];
        o.z = src[j+2] + bias_s[j+2];
        o.w = src[j+3] + bias_s[j+3];
        *(float4*)(dst + j) = o;
    }
}

// ---------------- Launch ----------------
extern "C" void kernel_launch(void* const* d_in, const int* in_sizes, int n_in,
                              void* d_out, int out_size) {
    const float* x  = (const float*)d_in[0];
    const float* G  = (const float*)d_in[1];
    const float* H  = (const float*)d_in[2];
    const float* b1 = (const float*)d_in[3];
    const float* W2 = (const float*)d_in[4];
    const float* b2 = (const float*)d_in[5];
    float* out = (float*)d_out;

    void *pWp, *pWc, *pW2c, *phc;
    cudaGetSymbolAddress(&pWp, g_Wpart);
    cudaGetSymbolAddress(&pWc, g_Wc);
    cudaGetSymbolAddress(&pW2c, g_W2c);
    cudaGetSymbolAddress(&phc, g_hc);

    cudaFuncSetAttribute(gemm1, cudaFuncAttributeMaxDynamicSharedMemorySize, SMEM_SZ);
    cudaFuncSetAttribute(gemm2, cudaFuncAttributeMaxDynamicSharedMemorySize, SMEM_SZ);

    krylov_part<<<dim3(8, 8, 16), 256>>>(G, H, (float*)pWp);
    pack_both<<<512, 256>>>((const float*)pWp, (__half*)pWc, W2, (__half*)pW2c);

    gemm1<<<dim3(4, BATCH / 128), 128, SMEM_SZ>>>(x, (const __half*)pWc, b1, (__half*)phc);
    gemm2<<<dim3(4, BATCH / 128), 128, SMEM_SZ>>>((const __half*)phc, (const __half*)pW2c, b2, out);
}

// round 14
// speedup vs baseline: 1.3382x; 1.3382x over previous
#include <cuda_runtime.h>
#include <cuda_fp16.h>
#include <mma.h>
#include <cstdint>
#include <cstddef>

using namespace nvcuda;

#define NDIM  512
#define BATCH 65536
#define LDAB  72                     // halves per padded row (64 data + 8 pad)
#define CHUNK_H (128 * LDAB)         // halves per chunk tile (128 rows)
#define CHUNK_B (CHUNK_H * 2)        // 18432 bytes

// Scratch (__device__ globals: allocation-free rule). Chunk-contiguous padded
// layouts: [tile][chunk][row][72] so cp.async.bulk fetches one chunk per copy.
__device__ float  g_Wpart[16 * NDIM * NDIM];
__device__ __half g_Wc [4 * 8 * CHUNK_H];               // W^T  chunks [ntile][c][n][72]
__device__ __half g_W2c[4 * 8 * CHUNK_H];               // W2^T chunks
__device__ __half g_xc[(size_t)512 * 8 * CHUNK_H];      // x fp16 chunks [mtile][c][m][72]
__device__ __half g_hc[(size_t)512 * 8 * CHUNK_H];      // h fp16 chunks

__device__ __forceinline__ uint32_t pack_h2(__half a, __half b) {
    return (uint32_t)__half_as_ushort(a) | ((uint32_t)__half_as_ushort(b) << 16);
}
__device__ __forceinline__ uint32_t smem_u32(const void* p) {
    uint32_t a;
    asm("{ .reg .u64 t; cvta.to.shared.u64 t, %1; cvt.u32.u64 %0, t; }" : "=r"(a) : "l"(p));
    return a;
}
#define MBAR_INIT(a, c) asm volatile("mbarrier.init.shared.b64 [%0], %1;" :: "r"(a), "r"(c) : "memory")
__device__ __forceinline__ void mbar_wait(uint32_t a, uint32_t ph) {
    uint32_t d;
    do {
        asm volatile("{ .reg .pred p; mbarrier.try_wait.parity.acquire.cta.shared::cta.b64 p, [%1], %2, 0x989680;"
                     " selp.b32 %0,1,0,p; }" : "=r"(d) : "r"(a), "r"(ph) : "memory");
    } while (!d);
}
__device__ __forceinline__ void mbar_expect_tx(uint32_t a, uint32_t bytes) {
    asm volatile("mbarrier.arrive.expect_tx.shared.b64 _, [%0], %1;" :: "r"(a), "r"(bytes) : "memory");
}
__device__ __forceinline__ void bulk_g2s(uint32_t dst, const void* src, uint32_t bytes, uint32_t mbar) {
    asm volatile("cp.async.bulk.shared::cluster.global.mbarrier::complete_tx::bytes [%0], [%1], %2, [%3];"
                 :: "r"(dst), "l"(src), "r"(bytes), "r"(mbar) : "memory");
}

#define XCONV_BLOCKS 16384           // BATCH*64/256

// ---------------- Kernel 1: fused xconv + Krylov partials (r11) ----------------
__global__ __launch_bounds__(256)
void xconv_krylov(const float* __restrict__ x, __half* __restrict__ xc,
                  const float* __restrict__ G, const float* __restrict__ H,
                  float* __restrict__ Wp) {
    const int tid = threadIdx.x;
    if (blockIdx.x < XCONV_BLOCKS) {
        int idx = blockIdx.x * 256 + tid;
        int m = idx >> 6, rem = idx & 63, c = rem >> 3, sub = rem & 7;
        const float* xp = x + (size_t)m * NDIM + c * 64 + sub * 8;
        float4 a = *(const float4*)xp;
        float4 b = *(const float4*)(xp + 4);
        uint4 o;
        o.x = pack_h2(__float2half_rn(a.x), __float2half_rn(a.y));
        o.y = pack_h2(__float2half_rn(a.z), __float2half_rn(a.w));
        o.z = pack_h2(__float2half_rn(b.x), __float2half_rn(b.y));
        o.w = pack_h2(__float2half_rn(b.z), __float2half_rn(b.w));
        size_t off = ((size_t)((m >> 7) * 8 + c) * 128 + (m & 127)) * LDAB + sub * 8;
        *(uint4*)(xc + off) = o;
        return;
    }
    // ---- Krylov: W[a,b] = sum_i sum_j ge_i[512+a-j] * hs_i[b+j] ----
    const int zb = blockIdx.x - XCONV_BLOCKS;   // 0..1023
    const int z  = zb >> 6;
    const int byy = (zb >> 3) & 7;
    const int bxx = zb & 7;
    const int i  = z & 3;
    const int j0 = (z >> 2) * 128;

    __shared__ float ge[1024], hs[1024];
    for (int k = tid; k < 1024; k += 256) {
        ge[k] = G[(k & 511) * 4 + i];
        hs[k] = (k < 512) ? H[k * 4 + i] : -H[(k - 512) * 4 + i];
    }
    __syncthreads();
    const int a0 = byy * 64 + (tid >> 4) * 4;
    const int b0 = bxx * 64 + (tid & 15) * 4;
    float acc[4][4] = {};
    float ga[4], hb[4];
#pragma unroll
    for (int d = 0; d < 4; ++d) ga[d] = ge[512 + a0 + d - j0];
#pragma unroll
    for (int e = 0; e < 4; ++e) hb[e] = hs[b0 + e + j0];
#pragma unroll 4
    for (int j = j0; j < j0 + 128; ++j) {
#pragma unroll
        for (int d = 0; d < 4; ++d)
#pragma unroll
            for (int e = 0; e < 4; ++e)
                acc[d][e] = fmaf(ga[d], hb[e], acc[d][e]);
        ga[3] = ga[2]; ga[2] = ga[1]; ga[1] = ga[0];
        ga[0] = ge[512 + a0 - (j + 1)];
        hb[0] = hb[1]; hb[1] = hb[2]; hb[2] = hb[3];
        hb[3] = hs[b0 + 3 + (j + 1)];
    }
    float* Ws = Wp + (size_t)z * NDIM * NDIM;
#pragma unroll
    for (int d = 0; d < 4; ++d)
#pragma unroll
        for (int e = 0; e < 4; ++e)
            Ws[(a0 + d) * NDIM + (b0 + e)] = acc[d][e];
}

// ---------------- Kernel 2: fused pack (W-sum+transpose | W2 transpose) ----------------
__global__ __launch_bounds__(256)
void pack_both(const float* __restrict__ Wp, __half* __restrict__ Wc,
               const float* __restrict__ W2, __half* __restrict__ W2c) {
    __shared__ float t[32][33];
    const int which = blockIdx.x >> 8;
    const int b = blockIdx.x & 255;
    const int bx = (b & 15) * 32, by = (b >> 4) * 32;
    const int tx = threadIdx.x & 31, ty = threadIdx.x >> 5;
    if (which == 0) {
        for (int r = ty; r < 32; r += 8) {
            size_t o = (size_t)(bx + r) * NDIM + by + tx;
            float s = 0.f;
#pragma unroll
            for (int z = 0; z < 16; ++z) s += Wp[o + (size_t)z * NDIM * NDIM];
            t[r][tx] = s;
        }
        __syncthreads();
        for (int r = ty; r < 32; r += 8) {
            int n = by + r, k = bx + tx;
            size_t off = ((size_t)((n >> 7) * 8 + (k >> 6)) * 128 + (n & 127)) * LDAB + (k & 63);
            Wc[off] = __float2half_rn(t[tx][r]);
        }
    } else {
        for (int r = ty; r < 32; r += 8)
            t[r][tx] = W2[(size_t)(bx + r) * NDIM + by + tx];
        __syncthreads();
        for (int r = ty; r < 32; r += 8) {
            int n = by + r, k = bx + tx;
            size_t off = ((size_t)((n >> 7) * 8 + (k >> 6)) * 128 + (n & 127)) * LDAB + (k & 63);
            W2c[off] = __float2half_rn(t[tx][r]);
        }
    }
}

// ---------------- Kernel 3: wmma GEMM, 128x128 tile, bulk pipeline + frag epilogue ----------------
// Bias is pre-loaded into acc fragments (16x128 replicated tile in buf0 pre-TMA).
// STAGE 1: relu applied elementwise on fragments; fp32->fp16 via SMEM pass -> h chunks.
// STAGE 2: direct store_matrix_sync to global (no SMEM roundtrip).
#define STG_SZ  36864u               // A chunk + B chunk
#define SMBAR   110592u              // after 3 stage buffers
#define SMEM_SZ 110624u
#define NCHUNK  8

template <int STAGE>
__global__ __launch_bounds__(128, 2)
void gemm_wmma(const __half* __restrict__ Ag, const __half* __restrict__ Bg,
               const float* __restrict__ bias, void* __restrict__ Cg) {
    extern __shared__ char smem[];
    const uint32_t sb = smem_u32(smem);
    __half* smh = (__half*)smem;
    const int tid = threadIdx.x;
    const int w  = tid >> 5;
    const int wm = w >> 1;           // warp row (2): 64 rows each
    const int wn = w & 1;            // warp col (2): 64 cols each
    const int bx = blockIdx.x, mt = blockIdx.y;
    const int n0 = bx * 128, m0 = mt * 128;

    // ---- bias-replicated 16x128 fp32 tile in (not yet used) buffer 0 ----
    float* bt = (float*)smem;
    {
        float bv = bias[n0 + tid];   // 128 threads cover 128 cols
#pragma unroll
        for (int r = 0; r < 16; ++r) bt[r * 128 + tid] = bv;
    }
    __syncthreads();

    wmma::fragment<wmma::accumulator, 16, 16, 16, float> acc[4][4];
#pragma unroll
    for (int j = 0; j < 4; ++j) {
        wmma::load_matrix_sync(acc[0][j], bt + wn * 64 + j * 16, 128, wmma::mem_row_major);
#pragma unroll
        for (int i = 1; i < 4; ++i) acc[i][j] = acc[0][j];
    }

    if (tid == 0) {
#pragma unroll
        for (int s = 0; s < 3; ++s) MBAR_INIT(sb + SMBAR + s * 8, 1);
    }
    __syncthreads();                 // bias reads done + mbars visible before TMA

    auto issue = [&](int c) {        // tid 0 only
        uint32_t mb  = sb + SMBAR + (c % 3) * 8;
        uint32_t buf = sb + (uint32_t)(c % 3) * STG_SZ;
        mbar_expect_tx(mb, 2 * CHUNK_B);
        bulk_g2s(buf,           Ag + ((size_t)mt * 8 + c) * CHUNK_H, CHUNK_B, mb);
        bulk_g2s(buf + CHUNK_B, Bg + ((size_t)bx * 8 + c) * CHUNK_H, CHUNK_B, mb);
    };
    if (tid == 0) { issue(0); issue(1); }

    for (int c = 0; c < NCHUNK; ++c) {
        mbar_wait(sb + SMBAR + (c % 3) * 8, (c / 3) & 1);
        __syncthreads();             // everyone past chunk c-1 -> buffer (c+2)%3 free
        if (tid == 0 && c + 2 < NCHUNK) issue(c + 2);

        const __half* As = smh + ((c % 3) * STG_SZ) / 2;
        const __half* Bs = As + CHUNK_H;
#pragma unroll
        for (int kk = 0; kk < 4; ++kk) {
            wmma::fragment<wmma::matrix_a, 16, 16, 16, __half, wmma::row_major> af[4];
            wmma::fragment<wmma::matrix_b, 16, 16, 16, __half, wmma::col_major> bf[4];
#pragma unroll
            for (int i = 0; i < 4; ++i)
                wmma::load_matrix_sync(af[i], As + (wm * 64 + i * 16) * LDAB + kk * 16, LDAB);
#pragma unroll
            for (int j = 0; j < 4; ++j)
                wmma::load_matrix_sync(bf[j], Bs + (wn * 64 + j * 16) * LDAB + kk * 16, LDAB);
#pragma unroll
            for (int i = 0; i < 4; ++i)
#pragma unroll
                for (int j = 0; j < 4; ++j)
                    wmma::mma_sync(acc[i][j], af[i], bf[j], acc[i][j]);
        }
    }

    if (STAGE == 2) {
        // ---- direct fragment stores to global (bias already inside acc) ----
        float* outp = (float*)Cg;
#pragma unroll
        for (int i = 0; i < 4; ++i)
#pragma unroll
            for (int j = 0; j < 4; ++j)
                wmma::store_matrix_sync(
                    outp + (size_t)(m0 + wm * 64 + i * 16) * NDIM + n0 + wn * 64 + j * 16,
                    acc[i][j], NDIM, wmma::mem_row_major);
        return;
    }

    // ---- STAGE 1: relu on fragments, then fp32->fp16 conversion via SMEM ----
#pragma unroll
    for (int i = 0; i < 4; ++i)
#pragma unroll
        for (int j = 0; j < 4; ++j)
#pragma unroll
            for (int e = 0; e < acc[i][j].num_elements; ++e)
                acc[i][j].x[e] = fmaxf(acc[i][j].x[e], 0.f);

    __syncthreads();                 // mainloop consumers done before smem reuse
    float* Cs = (float*)smem;        // 128 x 132 fp32
#pragma unroll
    for (int i = 0; i < 4; ++i)
#pragma unroll
        for (int j = 0; j < 4; ++j)
            wmma::store_matrix_sync(Cs + (wm * 64 + i * 16) * 132 + wn * 64 + j * 16,
                                    acc[i][j], 132, wmma::mem_row_major);
    __syncthreads();

    const int r = tid;               // one row per thread
    const float* src = Cs + r * 132;
    __half* hb = (__half*)Cg;        // chunk-contiguous padded layout
#pragma unroll
    for (int j = 0; j < 128; j += 8) {
        uint4 o;
        o.x = pack_h2(__float2half_rn(src[j+0]), __float2half_rn(src[j+1]));
        o.y = pack_h2(__float2half_rn(src[j+2]), __float2half_rn(src[j+3]));
        o.z = pack_h2(__float2half_rn(src[j+4]), __float2half_rn(src[j+5]));
        o.w = pack_h2(__float2half_rn(src[j+6]), __float2half_rn(src[j+7]));
        size_t off = ((size_t)(mt * 8 + bx * 2 + (j >> 6)) * 128 + r) * LDAB + (j & 63);
        *(uint4*)(hb + off) = o;
    }
}

// ---------------- Launch ----------------
extern "C" void kernel_launch(void* const* d_in, const int* in_sizes, int n_in,
                              void* d_out, int out_size) {
    const float* x  = (const float*)d_in[0];
    const float* G  = (const float*)d_in[1];
    const float* H  = (const float*)d_in[2];
    const float* b1 = (const float*)d_in[3];
    const float* W2 = (const float*)d_in[4];
    const float* b2 = (const float*)d_in[5];
    float* out = (float*)d_out;

    void *pWp, *pWc, *pW2c, *pxc, *phc;
    cudaGetSymbolAddress(&pWp, g_Wpart);
    cudaGetSymbolAddress(&pWc, g_Wc);
    cudaGetSymbolAddress(&pW2c, g_W2c);
    cudaGetSymbolAddress(&pxc, g_xc);
    cudaGetSymbolAddress(&phc, g_hc);

    cudaFuncSetAttribute(gemm_wmma<1>, cudaFuncAttributeMaxDynamicSharedMemorySize, SMEM_SZ);
    cudaFuncSetAttribute(gemm_wmma<2>, cudaFuncAttributeMaxDynamicSharedMemorySize, SMEM_SZ);

    xconv_krylov<<<XCONV_BLOCKS + 1024, 256>>>(x, (__half*)pxc, G, H, (float*)pWp);
    pack_both<<<512, 256>>>((const float*)pWp, (__half*)pWc, W2, (__half*)pW2c);

    gemm_wmma<1><<<dim3(4, BATCH / 128), 128, SMEM_SZ>>>((const __half*)pxc, (const __half*)pWc,  b1, phc);
    gemm_wmma<2><<<dim3(4, BATCH / 128), 128, SMEM_SZ>>>((const __half*)phc, (const __half*)pW2c, b2, out);
}

// round 15
// speedup vs baseline: 1.3863x; 1.0359x over previous
#include <cuda_runtime.h>
#include <cuda_fp16.h>
#include <mma.h>
#include <cstdint>
#include <cstddef>

using namespace nvcuda;

#define NDIM  512
#define BATCH 65536
#define LDAB  72                     // halves per padded row (64 data + 8 pad)
#define CHUNK_H (128 * LDAB)         // halves per chunk tile (128 rows)
#define CHUNK_B (CHUNK_H * 2)        // 18432 bytes

// Scratch (__device__ globals: allocation-free rule). Chunk-contiguous padded
// layouts: [tile][chunk][row][72] so cp.async.bulk fetches one chunk per copy.
__device__ float  g_Wpart[16 * NDIM * NDIM];
__device__ __half g_Wc [4 * 8 * CHUNK_H];               // W^T  chunks [ntile][c][n][72]
__device__ __half g_W2c[4 * 8 * CHUNK_H];               // W2^T chunks
__device__ __half g_xc[(size_t)512 * 8 * CHUNK_H];      // x fp16 chunks [mtile][c][m][72]
__device__ __half g_hc[(size_t)512 * 8 * CHUNK_H];      // h fp16 chunks

__device__ __forceinline__ uint32_t pack_h2(__half a, __half b) {
    return (uint32_t)__half_as_ushort(a) | ((uint32_t)__half_as_ushort(b) << 16);
}
__device__ __forceinline__ uint32_t smem_u32(const void* p) {
    uint32_t a;
    asm("{ .reg .u64 t; cvta.to.shared.u64 t, %1; cvt.u32.u64 %0, t; }" : "=r"(a) : "l"(p));
    return a;
}
#define MBAR_INIT(a, c) asm volatile("mbarrier.init.shared.b64 [%0], %1;" :: "r"(a), "r"(c) : "memory")
__device__ __forceinline__ void mbar_wait(uint32_t a, uint32_t ph) {
    uint32_t d;
    do {
        asm volatile("{ .reg .pred p; mbarrier.try_wait.parity.acquire.cta.shared::cta.b64 p, [%1], %2, 0x989680;"
                     " selp.b32 %0,1,0,p; }" : "=r"(d) : "r"(a), "r"(ph) : "memory");
    } while (!d);
}
__device__ __forceinline__ void mbar_expect_tx(uint32_t a, uint32_t bytes) {
    asm volatile("mbarrier.arrive.expect_tx.shared.b64 _, [%0], %1;" :: "r"(a), "r"(bytes) : "memory");
}
__device__ __forceinline__ void bulk_g2s(uint32_t dst, const void* src, uint32_t bytes, uint32_t mbar) {
    asm volatile("cp.async.bulk.shared::cluster.global.mbarrier::complete_tx::bytes [%0], [%1], %2, [%3];"
                 :: "r"(dst), "l"(src), "r"(bytes), "r"(mbar) : "memory");
}

#define XCONV_BLOCKS 16384           // BATCH*64/256

// ---------------- Kernel 1: fused xconv + Krylov partials ----------------
__global__ __launch_bounds__(256)
void xconv_krylov(const float* __restrict__ x, __half* __restrict__ xc,
                  const float* __restrict__ G, const float* __restrict__ H,
                  float* __restrict__ Wp) {
    const int tid = threadIdx.x;
    if (blockIdx.x < XCONV_BLOCKS) {
        int idx = blockIdx.x * 256 + tid;
        int m = idx >> 6, rem = idx & 63, c = rem >> 3, sub = rem & 7;
        const float* xp = x + (size_t)m * NDIM + c * 64 + sub * 8;
        float4 a = *(const float4*)xp;
        float4 b = *(const float4*)(xp + 4);
        uint4 o;
        o.x = pack_h2(__float2half_rn(a.x), __float2half_rn(a.y));
        o.y = pack_h2(__float2half_rn(a.z), __float2half_rn(a.w));
        o.z = pack_h2(__float2half_rn(b.x), __float2half_rn(b.y));
        o.w = pack_h2(__float2half_rn(b.z), __float2half_rn(b.w));
        size_t off = ((size_t)((m >> 7) * 8 + c) * 128 + (m & 127)) * LDAB + sub * 8;
        *(uint4*)(xc + off) = o;
        return;
    }
    // ---- Krylov: W[a,b] = sum_i sum_j ge_i[512+a-j] * hs_i[b+j] ----
    const int zb = blockIdx.x - XCONV_BLOCKS;   // 0..1023
    const int z  = zb >> 6;
    const int byy = (zb >> 3) & 7;
    const int bxx = zb & 7;
    const int i  = z & 3;
    const int j0 = (z >> 2) * 128;

    __shared__ float ge[1024], hs[1024];
    for (int k = tid; k < 1024; k += 256) {
        ge[k] = G[(k & 511) * 4 + i];
        hs[k] = (k < 512) ? H[k * 4 + i] : -H[(k - 512) * 4 + i];
    }
    __syncthreads();
    const int a0 = byy * 64 + (tid >> 4) * 4;
    const int b0 = bxx * 64 + (tid & 15) * 4;
    float acc[4][4] = {};
    float ga[4], hb[4];
#pragma unroll
    for (int d = 0; d < 4; ++d) ga[d] = ge[512 + a0 + d - j0];
#pragma unroll
    for (int e = 0; e < 4; ++e) hb[e] = hs[b0 + e + j0];
#pragma unroll 4
    for (int j = j0; j < j0 + 128; ++j) {
#pragma unroll
        for (int d = 0; d < 4; ++d)
#pragma unroll
            for (int e = 0; e < 4; ++e)
                acc[d][e] = fmaf(ga[d], hb[e], acc[d][e]);
        ga[3] = ga[2]; ga[2] = ga[1]; ga[1] = ga[0];
        ga[0] = ge[512 + a0 - (j + 1)];
        hb[0] = hb[1]; hb[1] = hb[2]; hb[2] = hb[3];
        hb[3] = hs[b0 + 3 + (j + 1)];
    }
    float* Ws = Wp + (size_t)z * NDIM * NDIM;
#pragma unroll
    for (int d = 0; d < 4; ++d)
#pragma unroll
        for (int e = 0; e < 4; ++e)
            Ws[(a0 + d) * NDIM + (b0 + e)] = acc[d][e];
}

// ---------------- Kernel 2: fused pack (W-sum+transpose | W2 transpose) ----------------
__global__ __launch_bounds__(256)
void pack_both(const float* __restrict__ Wp, __half* __restrict__ Wc,
               const float* __restrict__ W2, __half* __restrict__ W2c) {
    __shared__ float t[32][33];
    const int which = blockIdx.x >> 8;
    const int b = blockIdx.x & 255;
    const int bx = (b & 15) * 32, by = (b >> 4) * 32;
    const int tx = threadIdx.x & 31, ty = threadIdx.x >> 5;
    if (which == 0) {
        for (int r = ty; r < 32; r += 8) {
            size_t o = (size_t)(bx + r) * NDIM + by + tx;
            float s = 0.f;
#pragma unroll
            for (int z = 0; z < 16; ++z) s += Wp[o + (size_t)z * NDIM * NDIM];
            t[r][tx] = s;
        }
        __syncthreads();
        for (int r = ty; r < 32; r += 8) {
            int n = by + r, k = bx + tx;
            size_t off = ((size_t)((n >> 7) * 8 + (k >> 6)) * 128 + (n & 127)) * LDAB + (k & 63);
            Wc[off] = __float2half_rn(t[tx][r]);
        }
    } else {
        for (int r = ty; r < 32; r += 8)
            t[r][tx] = W2[(size_t)(bx + r) * NDIM + by + tx];
        __syncthreads();
        for (int r = ty; r < 32; r += 8) {
            int n = by + r, k = bx + tx;
            size_t off = ((size_t)((n >> 7) * 8 + (k >> 6)) * 128 + (n & 127)) * LDAB + (k & 63);
            W2c[off] = __float2half_rn(t[tx][r]);
        }
    }
}

// ---------------- Kernel 3: wmma GEMM, 128x128 tile, bulk pipeline, all-fragment epilogue ----------------
// Bias pre-loaded into acc fragments (16x128 replicated tile in buf0 pre-TMA).
// STAGE 1: relu + fp32->fp16 on fragments, direct store_matrix_sync into global h chunks.
// STAGE 2: direct store_matrix_sync to global fp32 out.
#define STG_SZ  36864u               // A chunk + B chunk
#define SMBAR   110592u              // after 3 stage buffers
#define SMEM_SZ 110624u
#define NCHUNK  8

template <int STAGE>
__global__ __launch_bounds__(128, 2)
void gemm_wmma(const __half* __restrict__ Ag, const __half* __restrict__ Bg,
               const float* __restrict__ bias, void* __restrict__ Cg) {
    extern __shared__ char smem[];
    const uint32_t sb = smem_u32(smem);
    __half* smh = (__half*)smem;
    const int tid = threadIdx.x;
    const int w  = tid >> 5;
    const int wm = w >> 1;           // warp row (2): 64 rows each
    const int wn = w & 1;            // warp col (2): 64 cols each
    const int bx = blockIdx.x, mt = blockIdx.y;
    const int n0 = bx * 128, m0 = mt * 128;

    // ---- bias-replicated 16x128 fp32 tile in (not yet used) buffer 0 ----
    float* bt = (float*)smem;
    {
        float bv = bias[n0 + tid];   // 128 threads cover 128 cols
#pragma unroll
        for (int r = 0; r < 16; ++r) bt[r * 128 + tid] = bv;
    }
    __syncthreads();

    wmma::fragment<wmma::accumulator, 16, 16, 16, float> acc[4][4];
#pragma unroll
    for (int j = 0; j < 4; ++j) {
        wmma::load_matrix_sync(acc[0][j], bt + wn * 64 + j * 16, 128, wmma::mem_row_major);
#pragma unroll
        for (int i = 1; i < 4; ++i) acc[i][j] = acc[0][j];
    }

    if (tid == 0) {
#pragma unroll
        for (int s = 0; s < 3; ++s) MBAR_INIT(sb + SMBAR + s * 8, 1);
    }
    __syncthreads();                 // bias reads done + mbars visible before TMA

    auto issue = [&](int c) {        // tid 0 only
        uint32_t mb  = sb + SMBAR + (c % 3) * 8;
        uint32_t buf = sb + (uint32_t)(c % 3) * STG_SZ;
        mbar_expect_tx(mb, 2 * CHUNK_B);
        bulk_g2s(buf,           Ag + ((size_t)mt * 8 + c) * CHUNK_H, CHUNK_B, mb);
        bulk_g2s(buf + CHUNK_B, Bg + ((size_t)bx * 8 + c) * CHUNK_H, CHUNK_B, mb);
    };
    if (tid == 0) { issue(0); issue(1); }

    for (int c = 0; c < NCHUNK; ++c) {
        mbar_wait(sb + SMBAR + (c % 3) * 8, (c / 3) & 1);
        __syncthreads();             // everyone past chunk c-1 -> buffer (c+2)%3 free
        if (tid == 0 && c + 2 < NCHUNK) issue(c + 2);

        const __half* As = smh + ((c % 3) * STG_SZ) / 2;
        const __half* Bs = As + CHUNK_H;
#pragma unroll
        for (int kk = 0; kk < 4; ++kk) {
            wmma::fragment<wmma::matrix_a, 16, 16, 16, __half, wmma::row_major> af[4];
            wmma::fragment<wmma::matrix_b, 16, 16, 16, __half, wmma::col_major> bf[4];
#pragma unroll
            for (int i = 0; i < 4; ++i)
                wmma::load_matrix_sync(af[i], As + (wm * 64 + i * 16) * LDAB + kk * 16, LDAB);
#pragma unroll
            for (int j = 0; j < 4; ++j)
                wmma::load_matrix_sync(bf[j], Bs + (wn * 64 + j * 16) * LDAB + kk * 16, LDAB);
#pragma unroll
            for (int i = 0; i < 4; ++i)
#pragma unroll
                for (int j = 0; j < 4; ++j)
                    wmma::mma_sync(acc[i][j], af[i], bf[j], acc[i][j]);
        }
    }

    if (STAGE == 2) {
        // ---- direct fragment stores to global (bias already inside acc) ----
        float* outp = (float*)Cg;
#pragma unroll
        for (int i = 0; i < 4; ++i)
#pragma unroll
            for (int j = 0; j < 4; ++j)
                wmma::store_matrix_sync(
                    outp + (size_t)(m0 + wm * 64 + i * 16) * NDIM + n0 + wn * 64 + j * 16,
                    acc[i][j], NDIM, wmma::mem_row_major);
        return;
    }

    // ---- STAGE 1: relu + fp32->fp16 on fragments, direct store into h chunks ----
    // Warp's 64-col slab (global cols n0 + wn*64 .. +63) lands entirely in chunk
    // piece (bx*2 + wn); within-chunk col offset = j*16; ldm = LDAB (72, mult of 8).
    __half* hb = (__half*)Cg;
    const size_t cbase = ((size_t)mt * 8 + (size_t)bx * 2 + wn) * CHUNK_H;
#pragma unroll
    for (int i = 0; i < 4; ++i)
#pragma unroll
        for (int j = 0; j < 4; ++j) {
            wmma::fragment<wmma::accumulator, 16, 16, 16, __half> hf;
#pragma unroll
            for (int e = 0; e < hf.num_elements; ++e)
                hf.x[e] = __float2half_rn(fmaxf(acc[i][j].x[e], 0.f));
            wmma::store_matrix_sync(
                hb + cbase + (size_t)(wm * 64 + i * 16) * LDAB + j * 16,
                hf, LDAB, wmma::mem_row_major);
        }
}

// ---------------- Launch ----------------
extern "C" void kernel_launch(void* const* d_in, const int* in_sizes, int n_in,
                              void* d_out, int out_size) {
    const float* x  = (const float*)d_in[0];
    const float* G  = (const float*)d_in[1];
    const float* H  = (const float*)d_in[2];
    const float* b1 = (const float*)d_in[3];
    const float* W2 = (const float*)d_in[4];
    const float* b2 = (const float*)d_in[5];
    float* out = (float*)d_out;

    void *pWp, *pWc, *pW2c, *pxc, *phc;
    cudaGetSymbolAddress(&pWp, g_Wpart);
    cudaGetSymbolAddress(&pWc, g_Wc);
    cudaGetSymbolAddress(&pW2c, g_W2c);
    cudaGetSymbolAddress(&pxc, g_xc);
    cudaGetSymbolAddress(&phc, g_hc);

    cudaFuncSetAttribute(gemm_wmma<1>, cudaFuncAttributeMaxDynamicSharedMemorySize, SMEM_SZ);
    cudaFuncSetAttribute(gemm_wmma<2>, cudaFuncAttributeMaxDynamicSharedMemorySize, SMEM_SZ);

    xconv_krylov<<<XCONV_BLOCKS + 1024, 256>>>(x, (__half*)pxc, G, H, (float*)pWp);
    pack_both<<<512, 256>>>((const float*)pWp, (__half*)pWc, W2, (__half*)pW2c);

    gemm_wmma<1><<<dim3(4, BATCH / 128), 128, SMEM_SZ>>>((const __half*)pxc, (const __half*)pWc,  b1, phc);
    gemm_wmma<2><<<dim3(4, BATCH / 128), 128, SMEM_SZ>>>((const __half*)phc, (const __half*)pW2c, b2, out);
}

// round 17
// speedup vs baseline: 1.3889x; 1.0019x over previous
#include <cuda_runtime.h>
#include <cuda_fp16.h>
#include <mma.h>
#include <cstdint>
#include <cstddef>

using namespace nvcuda;

#define NDIM  512
#define BATCH 65536
#define LDAB  72                     // halves per padded row (64 data + 8 pad)
#define CHUNK_H (128 * LDAB)         // halves per chunk tile (128 rows)
#define CHUNK_B (CHUNK_H * 2)        // 18432 bytes

// Scratch (__device__ globals: allocation-free rule). Chunk-contiguous padded
// layouts: [tile][chunk][row][72] so cp.async.bulk fetches one chunk per copy.
__device__ float  g_Wpart[16 * NDIM * NDIM];
__device__ __half g_Wc [4 * 8 * CHUNK_H];               // W^T  chunks [ntile][c][n][72]
__device__ __half g_W2c[4 * 8 * CHUNK_H];               // W2^T chunks
__device__ __half g_xc[(size_t)512 * 8 * CHUNK_H];      // x fp16 chunks [mtile][c][m][72]
__device__ __half g_hc[(size_t)512 * 8 * CHUNK_H];      // h fp16 chunks

__device__ __forceinline__ uint32_t pack_h2(__half a, __half b) {
    return (uint32_t)__half_as_ushort(a) | ((uint32_t)__half_as_ushort(b) << 16);
}
__device__ __forceinline__ uint32_t smem_u32(const void* p) {
    uint32_t a;
    asm("{ .reg .u64 t; cvta.to.shared.u64 t, %1; cvt.u32.u64 %0, t; }" : "=r"(a) : "l"(p));
    return a;
}
#define MBAR_INIT(a, c) asm volatile("mbarrier.init.shared.b64 [%0], %1;" :: "r"(a), "r"(c) : "memory")
__device__ __forceinline__ void mbar_wait(uint32_t a, uint32_t ph) {
    uint32_t d;
    do {
        asm volatile("{ .reg .pred p; mbarrier.try_wait.parity.acquire.cta.shared::cta.b64 p, [%1], %2, 0x989680;"
                     " selp.b32 %0,1,0,p; }" : "=r"(d) : "r"(a), "r"(ph) : "memory");
    } while (!d);
}
__device__ __forceinline__ void mbar_expect_tx(uint32_t a, uint32_t bytes) {
    asm volatile("mbarrier.arrive.expect_tx.shared.b64 _, [%0], %1;" :: "r"(a), "r"(bytes) : "memory");
}
__device__ __forceinline__ void bulk_g2s(uint32_t dst, const void* src, uint32_t bytes, uint32_t mbar) {
    asm volatile("cp.async.bulk.shared::cluster.global.mbarrier::complete_tx::bytes [%0], [%1], %2, [%3];"
                 :: "r"(dst), "l"(src), "r"(bytes), "r"(mbar) : "memory");
}

#define XCONV_BLOCKS 16384           // BATCH*64/256

// ---------------- Kernel 1: fused xconv + Krylov partials ----------------
__global__ __launch_bounds__(256)
void xconv_krylov(const float* __restrict__ x, __half* __restrict__ xc,
                  const float* __restrict__ G, const float* __restrict__ H,
                  float* __restrict__ Wp) {
    const int tid = threadIdx.x;
    if (blockIdx.x < XCONV_BLOCKS) {
        int idx = blockIdx.x * 256 + tid;
        int m = idx >> 6, rem = idx & 63, c = rem >> 3, sub = rem & 7;
        const float* xp = x + (size_t)m * NDIM + c * 64 + sub * 8;
        float4 a = *(const float4*)xp;
        float4 b = *(const float4*)(xp + 4);
        uint4 o;
        o.x = pack_h2(__float2half_rn(a.x), __float2half_rn(a.y));
        o.y = pack_h2(__float2half_rn(a.z), __float2half_rn(a.w));
        o.z = pack_h2(__float2half_rn(b.x), __float2half_rn(b.y));
        o.w = pack_h2(__float2half_rn(b.z), __float2half_rn(b.w));
        size_t off = ((size_t)((m >> 7) * 8 + c) * 128 + (m & 127)) * LDAB + sub * 8;
        *(uint4*)(xc + off) = o;
        return;
    }
    // ---- Krylov: W[a,b] = sum_i sum_j ge_i[512+a-j] * hs_i[b+j] ----
    const int zb = blockIdx.x - XCONV_BLOCKS;   // 0..1023
    const int z  = zb >> 6;
    const int byy = (zb >> 3) & 7;
    const int bxx = zb & 7;
    const int i  = z & 3;
    const int j0 = (z >> 2) * 128;

    __shared__ float ge[1024], hs[1024];
    for (int k = tid; k < 1024; k += 256) {
        ge[k] = G[(k & 511) * 4 + i];
        hs[k] = (k < 512) ? H[k * 4 + i] : -H[(k - 512) * 4 + i];
    }
    __syncthreads();
    const int a0 = byy * 64 + (tid >> 4) * 4;
    const int b0 = bxx * 64 + (tid & 15) * 4;
    float acc[4][4] = {};
    float ga[4], hb[4];
#pragma unroll
    for (int d = 0; d < 4; ++d) ga[d] = ge[512 + a0 + d - j0];
#pragma unroll
    for (int e = 0; e < 4; ++e) hb[e] = hs[b0 + e + j0];
#pragma unroll 4
    for (int j = j0; j < j0 + 128; ++j) {
#pragma unroll
        for (int d = 0; d < 4; ++d)
#pragma unroll
            for (int e = 0; e < 4; ++e)
                acc[d][e] = fmaf(ga[d], hb[e], acc[d][e]);
        ga[3] = ga[2]; ga[2] = ga[1]; ga[1] = ga[0];
        ga[0] = ge[512 + a0 - (j + 1)];
        hb[0] = hb[1]; hb[1] = hb[2]; hb[2] = hb[3];
        hb[3] = hs[b0 + 3 + (j + 1)];
    }
    float* Ws = Wp + (size_t)z * NDIM * NDIM;
#pragma unroll
    for (int d = 0; d < 4; ++d)
#pragma unroll
        for (int e = 0; e < 4; ++e)
            Ws[(a0 + d) * NDIM + (b0 + e)] = acc[d][e];
}

// ---------------- Kernel 2: fused pack (W-sum+transpose | W2 transpose) ----------------
__global__ __launch_bounds__(256)
void pack_both(const float* __restrict__ Wp, __half* __restrict__ Wc,
               const float* __restrict__ W2, __half* __restrict__ W2c) {
    __shared__ float t[32][33];
    const int which = blockIdx.x >> 8;
    const int b = blockIdx.x & 255;
    const int bx = (b & 15) * 32, by = (b >> 4) * 32;
    const int tx = threadIdx.x & 31, ty = threadIdx.x >> 5;
    if (which == 0) {
        for (int r = ty; r < 32; r += 8) {
            size_t o = (size_t)(bx + r) * NDIM + by + tx;
            float s = 0.f;
#pragma unroll
            for (int z = 0; z < 16; ++z) s += Wp[o + (size_t)z * NDIM * NDIM];
            t[r][tx] = s;
        }
        __syncthreads();
        for (int r = ty; r < 32; r += 8) {
            int n = by + r, k = bx + tx;
            size_t off = ((size_t)((n >> 7) * 8 + (k >> 6)) * 128 + (n & 127)) * LDAB + (k & 63);
            Wc[off] = __float2half_rn(t[tx][r]);
        }
    } else {
        for (int r = ty; r < 32; r += 8)
            t[r][tx] = W2[(size_t)(bx + r) * NDIM + by + tx];
        __syncthreads();
        for (int r = ty; r < 32; r += 8) {
            int n = by + r, k = bx + tx;
            size_t off = ((size_t)((n >> 7) * 8 + (k >> 6)) * 128 + (n & 127)) * LDAB + (k & 63);
            W2c[off] = __float2half_rn(t[tx][r]);
        }
    }
}

// ---------------- Kernel 3: warp-specialized wmma GEMM (counter-guarded) ----------------
// 160 threads: warps 0-3 compute (64x64 tiles), warp 4 = TMA producer.
// full[s] mbarriers (count 1 + expect_tx) exactly as the proven r15 path.
// Buffer-reuse guard: monotonic smem counters cnt[s]; each compute warp lane0
// atomicAdds after consuming a chunk; producer spins until cnt[s] >= 4*(c/3).
// No __syncthreads in the mainloop. Bias pre-loaded into acc fragments.
// STAGE 1: relu+cvt on frags -> h chunks direct. STAGE 2: direct frag store.
#define STG_SZ  36864u               // A chunk + B chunk
#define SMBAR   110592u              // 3 full mbars (24 B)
#define SCNT    110616u              // 3 int counters (12 B)
#define SMEM_SZ 110656u
#define NCHUNK  8

template <int STAGE>
__global__ __launch_bounds__(160, 2)
void gemm_wmma(const __half* __restrict__ Ag, const __half* __restrict__ Bg,
               const float* __restrict__ bias, void* __restrict__ Cg) {
    extern __shared__ char smem[];
    const uint32_t sb = smem_u32(smem);
    __half* smh = (__half*)smem;
    const int tid = threadIdx.x;
    const int w  = tid >> 5;         // 0..4
    const int wm = w >> 1;           // compute: warp row (2)
    const int wn = w & 1;            // compute: warp col (2)
    const int bx = blockIdx.x, mt = blockIdx.y;
    const int n0 = bx * 128, m0 = mt * 128;

    int* cnt = (int*)(smem + SCNT);

    // ---- bias-replicated 16x128 fp32 tile in (not yet used) buffer 0 ----
    float* bt = (float*)smem;
    if (tid < 128) {
        float bv = bias[n0 + tid];
#pragma unroll
        for (int r = 0; r < 16; ++r) bt[r * 128 + tid] = bv;
    }
    if (tid == 0) {
#pragma unroll
        for (int s = 0; s < 3; ++s) {
            MBAR_INIT(sb + SMBAR + s * 8, 1);
            cnt[s] = 0;
        }
    }
    __syncthreads();

    wmma::fragment<wmma::accumulator, 16, 16, 16, float> acc[4][4];
    if (w < 4) {
#pragma unroll
        for (int j = 0; j < 4; ++j) {
            wmma::load_matrix_sync(acc[0][j], bt + wn * 64 + j * 16, 128, wmma::mem_row_major);
#pragma unroll
            for (int i = 1; i < 4; ++i) acc[i][j] = acc[0][j];
        }
    }
    __syncthreads();                 // bias reads done before producer's first TMA

    if (w == 4) {
        // ---------------- producer warp ----------------
        volatile int* vcnt = (volatile int*)cnt;
        for (int c = 0; c < NCHUNK; ++c) {
            const int s = c % 3;
            const int need = (c / 3) * 4;          // consumers done with prior occupant
            while (vcnt[s] < need) { }
            if ((tid & 31) == 0) {
                uint32_t mb  = sb + SMBAR + s * 8;
                uint32_t buf = sb + (uint32_t)s * STG_SZ;
                mbar_expect_tx(mb, 2 * CHUNK_B);
                bulk_g2s(buf,           Ag + ((size_t)mt * 8 + c) * CHUNK_H, CHUNK_B, mb);
                bulk_g2s(buf + CHUNK_B, Bg + ((size_t)bx * 8 + c) * CHUNK_H, CHUNK_B, mb);
            }
        }
        return;
    }

    // ---------------- compute warps ----------------
    for (int c = 0; c < NCHUNK; ++c) {
        const int s = c % 3;
        mbar_wait(sb + SMBAR + s * 8, (c / 3) & 1);

        const __half* As = smh + (s * STG_SZ) / 2;
        const __half* Bs = As + CHUNK_H;
#pragma unroll
        for (int kk = 0; kk < 4; ++kk) {
            wmma::fragment<wmma::matrix_a, 16, 16, 16, __half, wmma::row_major> af[4];
            wmma::fragment<wmma::matrix_b, 16, 16, 16, __half, wmma::col_major> bf[4];
#pragma unroll
            for (int i = 0; i < 4; ++i)
                wmma::load_matrix_sync(af[i], As + (wm * 64 + i * 16) * LDAB + kk * 16, LDAB);
#pragma unroll
            for (int j = 0; j < 4; ++j)
                wmma::load_matrix_sync(bf[j], Bs + (wn * 64 + j * 16) * LDAB + kk * 16, LDAB);
#pragma unroll
            for (int i = 0; i < 4; ++i)
#pragma unroll
                for (int j = 0; j < 4; ++j)
                    wmma::mma_sync(acc[i][j], af[i], bf[j], acc[i][j]);
        }
        __threadfence_block();                     // order stage reads before count
        if ((tid & 31) == 0) atomicAdd(cnt + s, 1);
    }

    if (STAGE == 2) {
        float* outp = (float*)Cg;
#pragma unroll
        for (int i = 0; i < 4; ++i)
#pragma unroll
            for (int j = 0; j < 4; ++j)
                wmma::store_matrix_sync(
                    outp + (size_t)(m0 + wm * 64 + i * 16) * NDIM + n0 + wn * 64 + j * 16,
                    acc[i][j], NDIM, wmma::mem_row_major);
        return;
    }

    // STAGE 1: relu + fp32->fp16 on fragments, direct store into h chunks
    __half* hb = (__half*)Cg;
    const size_t cbase = ((size_t)mt * 8 + (size_t)bx * 2 + wn) * CHUNK_H;
#pragma unroll
    for (int i = 0; i < 4; ++i)
#pragma unroll
        for (int j = 0; j < 4; ++j) {
            wmma::fragment<wmma::accumulator, 16, 16, 16, __half> hf;
#pragma unroll
            for (int e = 0; e < hf.num_elements; ++e)
                hf.x[e] = __float2half_rn(fmaxf(acc[i][j].x[e], 0.f));
            wmma::store_matrix_sync(
                hb + cbase + (size_t)(wm * 64 + i * 16) * LDAB + j * 16,
                hf, LDAB, wmma::mem_row_major);
        }
}

// ---------------- Launch ----------------
extern "C" void kernel_launch(void* const* d_in, const int* in_sizes, int n_in,
                              void* d_out, int out_size) {
    const float* x  = (const float*)d_in[0];
    const float* G  = (const float*)d_in[1];
    const float* H  = (const float*)d_in[2];
    const float* b1 = (const float*)d_in[3];
    const float* W2 = (const float*)d_in[4];
    const float* b2 = (const float*)d_in[5];
    float* out = (float*)d_out;

    void *pWp, *pWc, *pW2c, *pxc, *phc;
    cudaGetSymbolAddress(&pWp, g_Wpart);
    cudaGetSymbolAddress(&pWc, g_Wc);
    cudaGetSymbolAddress(&pW2c, g_W2c);
    cudaGetSymbolAddress(&pxc, g_xc);
    cudaGetSymbolAddress(&phc, g_hc);

    cudaFuncSetAttribute(gemm_wmma<1>, cudaFuncAttributeMaxDynamicSharedMemorySize, SMEM_SZ);
    cudaFuncSetAttribute(gemm_wmma<2>, cudaFuncAttributeMaxDynamicSharedMemorySize, SMEM_SZ);

    xconv_krylov<<<XCONV_BLOCKS + 1024, 256>>>(x, (__half*)pxc, G, H, (float*)pWp);
    pack_both<<<512, 256>>>((const float*)pWp, (__half*)pWc, W2, (__half*)pW2c);

    gemm_wmma<1><<<dim3(4, BATCH / 128), 160, SMEM_SZ>>>((const __half*)pxc, (const __half*)pWc,  b1, phc);
    gemm_wmma<2><<<dim3(4, BATCH / 128), 160, SMEM_SZ>>>((const __half*)phc, (const __half*)pW2c, b2, out);
}